// round 1
// baseline (speedup 1.0000x reference)
#include <cuda_runtime.h>
#include <cstdint>

#define S_LEN 2048
#define DM    4096
#define HQ    32
#define HKV_N 8
#define HD    128
#define BM    64
#define BN    64

// ---------------- scratch (static device memory; no allocations) ------------
__device__ float g_q_lin[S_LEN * DM];            // 2048 x 4096
__device__ float g_k_lin[S_LEN * HKV_N * HD];    // 2048 x 1024
__device__ float g_v_lin[S_LEN * HKV_N * HD];    // 2048 x 1024
__device__ float g_qt[HQ * S_LEN * HD];          // 32 x 2048 x 128
__device__ float g_kt[HKV_N * S_LEN * HD];       // 8 x 2048 x 128
__device__ float g_ao[S_LEN * HQ * HD];          // 2048 x 4096

// ---------------- generic fp32 GEMM: C[M,N] = A[M,K] * B[N,K]^T --------------
// A row-major MxK, B row-major NxK (torch Linear weight layout), C row-major.
// 128x128 block tile, K-step 8, 256 threads, 8x8 microtile.
__global__ __launch_bounds__(256) void sgemm_nt(
    const float* __restrict__ A, const float* __restrict__ B,
    float* __restrict__ C, int M, int N, int K)
{
    __shared__ float As[8][128];
    __shared__ float Bs[8][128];

    const int tid = threadIdx.x;
    const int tx = tid & 15;
    const int ty = tid >> 4;
    const int bm = blockIdx.y * 128;
    const int bn = blockIdx.x * 128;

    const int lrow = tid >> 1;            // 0..127
    const int lk   = (tid & 1) * 4;       // 0 or 4
    const float* Ag = A + (size_t)(bm + lrow) * K + lk;
    const float* Bg = B + (size_t)(bn + lrow) * K + lk;

    float acc[8][8];
    #pragma unroll
    for (int i = 0; i < 8; i++)
        #pragma unroll
        for (int j = 0; j < 8; j++) acc[i][j] = 0.f;

    for (int k0 = 0; k0 < K; k0 += 8) {
        const float4 a4 = *reinterpret_cast<const float4*>(Ag + k0);
        const float4 b4 = *reinterpret_cast<const float4*>(Bg + k0);
        __syncthreads();
        As[lk + 0][lrow] = a4.x; As[lk + 1][lrow] = a4.y;
        As[lk + 2][lrow] = a4.z; As[lk + 3][lrow] = a4.w;
        Bs[lk + 0][lrow] = b4.x; Bs[lk + 1][lrow] = b4.y;
        Bs[lk + 2][lrow] = b4.z; Bs[lk + 3][lrow] = b4.w;
        __syncthreads();

        #pragma unroll
        for (int kk = 0; kk < 8; kk++) {
            float af[8], bf[8];
            #pragma unroll
            for (int i = 0; i < 8; i++) af[i] = As[kk][ty * 8 + i];
            #pragma unroll
            for (int j = 0; j < 8; j++) bf[j] = Bs[kk][tx + 16 * j];
            #pragma unroll
            for (int i = 0; i < 8; i++)
                #pragma unroll
                for (int j = 0; j < 8; j++) acc[i][j] += af[i] * bf[j];
        }
    }

    #pragma unroll
    for (int i = 0; i < 8; i++) {
        const size_t row = (size_t)(bm + ty * 8 + i) * N;
        #pragma unroll
        for (int j = 0; j < 8; j++)
            C[row + bn + tx + 16 * j] = acc[i][j];
    }
}

// --------------- RMSNorm over last dim (128) + transpose to [H][S][D] --------
__global__ __launch_bounds__(128) void rmsnorm_transpose(
    const float* __restrict__ in, const float* __restrict__ w,
    float* __restrict__ out, int rowStride)
{
    const int s = blockIdx.x;
    const int h = blockIdx.y;
    const int d = threadIdx.x;

    const float v = in[(size_t)s * rowStride + h * HD + d];
    float ss = v * v;
    #pragma unroll
    for (int off = 16; off; off >>= 1)
        ss += __shfl_xor_sync(0xffffffffu, ss, off);
    __shared__ float ws[4];
    if ((d & 31) == 0) ws[d >> 5] = ss;
    __syncthreads();
    const float tot = ws[0] + ws[1] + ws[2] + ws[3];
    const float inv = rsqrtf(tot * (1.0f / 128.0f) + 1e-6f);
    out[((size_t)h * S_LEN + s) * HD + d] = v * inv * w[d];
}

// --------------- flash attention with ALiBi + causal mask (GQA) --------------
// Q: [HQ][S][HD], Kt: [HKV][S][HD], Vlin: [S][HKV*HD], O: [S][HQ*HD]
__global__ __launch_bounds__(256) void attn_kernel(
    const float* __restrict__ Q, const float* __restrict__ Kt,
    const float* __restrict__ Vlin, float* __restrict__ O)
{
    extern __shared__ float sm[];
    float* Qs = sm;                      // [BM][129]
    float* Ks = Qs + BM * 129;           // [BN][129]
    float* Vs = Ks + BN * 129;           // [BN][HD]
    float* Ps = Vs + BN * HD;            // [BM][65]

    const int qt = blockIdx.x;
    const int h  = blockIdx.y;
    const int hk = h >> 2;
    const float slope = exp2f(-0.25f * (float)(h + 1));
    const float scale = 0.08838834764831845f; // 1/sqrt(128)

    const int tid = threadIdx.x;
    const int tx = tid & 15;
    const int ty = tid >> 4;

    // load Q tile (64 x 128)
    for (int idx = tid; idx < BM * HD / 4; idx += 256) {
        const int r = idx >> 5;
        const int c = (idx & 31) << 2;
        const float4 q4 = *reinterpret_cast<const float4*>(
            Q + ((size_t)h * S_LEN + (size_t)qt * BM + r) * HD + c);
        Qs[r * 129 + c + 0] = q4.x; Qs[r * 129 + c + 1] = q4.y;
        Qs[r * 129 + c + 2] = q4.z; Qs[r * 129 + c + 3] = q4.w;
    }

    float o_acc[4][8];
    float m_i[4], l_i[4];
    #pragma unroll
    for (int i = 0; i < 4; i++) {
        m_i[i] = -1e30f; l_i[i] = 0.f;
        #pragma unroll
        for (int m = 0; m < 8; m++) o_acc[i][m] = 0.f;
    }

    const int nkt = qt + 1;   // causal: only key tiles <= query tile
    for (int kt = 0; kt < nkt; kt++) {
        __syncthreads();
        // load K, V tiles (64 x 128 each)
        for (int idx = tid; idx < BN * HD / 4; idx += 256) {
            const int r = idx >> 5;
            const int c = (idx & 31) << 2;
            const float4 k4 = *reinterpret_cast<const float4*>(
                Kt + ((size_t)hk * S_LEN + (size_t)kt * BN + r) * HD + c);
            Ks[r * 129 + c + 0] = k4.x; Ks[r * 129 + c + 1] = k4.y;
            Ks[r * 129 + c + 2] = k4.z; Ks[r * 129 + c + 3] = k4.w;
            const float4 v4 = *reinterpret_cast<const float4*>(
                Vlin + ((size_t)(kt * BN + r)) * (HKV_N * HD) + hk * HD + c);
            Vs[r * HD + c + 0] = v4.x; Vs[r * HD + c + 1] = v4.y;
            Vs[r * HD + c + 2] = v4.z; Vs[r * HD + c + 3] = v4.w;
        }
        __syncthreads();

        // scores: 4x4 per thread, rows ty+16i, cols tx+16j
        float s_acc[4][4];
        #pragma unroll
        for (int i = 0; i < 4; i++)
            #pragma unroll
            for (int j = 0; j < 4; j++) s_acc[i][j] = 0.f;

        #pragma unroll 4
        for (int d = 0; d < HD; d++) {
            float qf[4], kf[4];
            #pragma unroll
            for (int i = 0; i < 4; i++) qf[i] = Qs[(ty + 16 * i) * 129 + d];
            #pragma unroll
            for (int j = 0; j < 4; j++) kf[j] = Ks[(tx + 16 * j) * 129 + d];
            #pragma unroll
            for (int i = 0; i < 4; i++)
                #pragma unroll
                for (int j = 0; j < 4; j++) s_acc[i][j] += qf[i] * kf[j];
        }

        const int q0 = qt * BM, k0 = kt * BN;
        #pragma unroll
        for (int i = 0; i < 4; i++) {
            const int qpos = q0 + ty + 16 * i;
            float rmax = -1e30f;
            #pragma unroll
            for (int j = 0; j < 4; j++) {
                const int kpos = k0 + tx + 16 * j;
                const float bias = (kpos > qpos) ? -1e30f
                                                 : slope * (float)(kpos - qpos);
                s_acc[i][j] = s_acc[i][j] * scale + bias;
                rmax = fmaxf(rmax, s_acc[i][j]);
            }
            #pragma unroll
            for (int off = 8; off; off >>= 1)
                rmax = fmaxf(rmax, __shfl_xor_sync(0xffffffffu, rmax, off));

            const float mnew = fmaxf(m_i[i], rmax);
            const float corr = __expf(m_i[i] - mnew);
            m_i[i] = mnew;

            float rsum = 0.f;
            #pragma unroll
            for (int j = 0; j < 4; j++) {
                const float p = __expf(s_acc[i][j] - mnew);
                Ps[(ty + 16 * i) * 65 + tx + 16 * j] = p;
                rsum += p;
            }
            #pragma unroll
            for (int off = 8; off; off >>= 1)
                rsum += __shfl_xor_sync(0xffffffffu, rsum, off);

            l_i[i] = l_i[i] * corr + rsum;
            #pragma unroll
            for (int m = 0; m < 8; m++) o_acc[i][m] *= corr;
        }
        __syncthreads();

        // O += P @ V : rows ty+16i, cols tx+16m
        #pragma unroll 4
        for (int jj = 0; jj < BN; jj++) {
            float pf[4], vf[8];
            #pragma unroll
            for (int i = 0; i < 4; i++) pf[i] = Ps[(ty + 16 * i) * 65 + jj];
            #pragma unroll
            for (int m = 0; m < 8; m++) vf[m] = Vs[jj * HD + tx + 16 * m];
            #pragma unroll
            for (int i = 0; i < 4; i++)
                #pragma unroll
                for (int m = 0; m < 8; m++) o_acc[i][m] += pf[i] * vf[m];
        }
    }

    #pragma unroll
    for (int i = 0; i < 4; i++) {
        const float inv = 1.0f / l_i[i];
        const size_t r = (size_t)(qt * BM + ty + 16 * i);
        #pragma unroll
        for (int m = 0; m < 8; m++)
            O[r * (HQ * HD) + h * HD + tx + 16 * m] = o_acc[i][m] * inv;
    }
}

// attention dynamic smem: Qs + Ks + Vs + Ps
static const size_t ATTN_SMEM =
    (size_t)(BM * 129 + BN * 129 + BN * HD + BM * 65) * sizeof(float);

extern "C" void kernel_launch(void* const* d_in, const int* in_sizes, int n_in,
                              void* d_out, int out_size)
{
    (void)in_sizes; (void)n_in; (void)out_size;
    const float* x  = (const float*)d_in[0];
    const float* Wq = (const float*)d_in[1];
    const float* Wk = (const float*)d_in[2];
    const float* Wv = (const float*)d_in[3];
    const float* Wo = (const float*)d_in[4];
    const float* qw = (const float*)d_in[5];
    const float* kw = (const float*)d_in[6];
    float* out = (float*)d_out;

    float *q_lin, *k_lin, *v_lin, *qt_, *kt_, *ao;
    cudaGetSymbolAddress((void**)&q_lin, g_q_lin);
    cudaGetSymbolAddress((void**)&k_lin, g_k_lin);
    cudaGetSymbolAddress((void**)&v_lin, g_v_lin);
    cudaGetSymbolAddress((void**)&qt_,   g_qt);
    cudaGetSymbolAddress((void**)&kt_,   g_kt);
    cudaGetSymbolAddress((void**)&ao,    g_ao);

    cudaFuncSetAttribute(attn_kernel,
        cudaFuncAttributeMaxDynamicSharedMemorySize, (int)ATTN_SMEM);

    dim3 blk(256);
    // QKV projections: C = x @ W^T
    sgemm_nt<<<dim3(DM / 128, S_LEN / 128), blk>>>(x, Wq, q_lin, S_LEN, DM, DM);
    sgemm_nt<<<dim3((HKV_N * HD) / 128, S_LEN / 128), blk>>>(x, Wk, k_lin, S_LEN, HKV_N * HD, DM);
    sgemm_nt<<<dim3((HKV_N * HD) / 128, S_LEN / 128), blk>>>(x, Wv, v_lin, S_LEN, HKV_N * HD, DM);

    // RMSNorm + head-major transpose
    rmsnorm_transpose<<<dim3(S_LEN, HQ), 128>>>(q_lin, qw, qt_, DM);
    rmsnorm_transpose<<<dim3(S_LEN, HKV_N), 128>>>(k_lin, kw, kt_, HKV_N * HD);

    // flash attention (writes [S][HQ*HD] directly)
    attn_kernel<<<dim3(S_LEN / BM, HQ), 256, ATTN_SMEM>>>(qt_, kt_, v_lin, ao);

    // output projection: out = ao @ Wo^T   (Wo given as [DM][HQ*HD])
    sgemm_nt<<<dim3(DM / 128, S_LEN / 128), blk>>>(ao, Wo, out, S_LEN, DM, DM);
}

// round 3
// speedup vs baseline: 2.3314x; 2.3314x over previous
#include <cuda_runtime.h>
#include <cstdint>

#define S_LEN 2048
#define DM    4096
#define HQ    32
#define HKV_N 8
#define HD    128
#define BM    64
#define BN    64

// tf32 mma.sync GEMM config
#define TM 128
#define TN 128
#define KC 32
#define LDP 36                    // padded smem row stride (floats) -> conflict-free frags
#define A_STAGE (TM * LDP)        // 4608 floats
#define B_STAGE (TN * LDP)
#define STAGE_F (A_STAGE + B_STAGE)

// ---------------- scratch (static device memory; no allocations) ------------
__device__ __align__(256) float g_rx [S_LEN * DM];
__device__ __align__(256) float g_rwq[DM * DM];
__device__ __align__(256) float g_rwk[HKV_N * HD * DM];
__device__ __align__(256) float g_rwv[HKV_N * HD * DM];
__device__ __align__(256) float g_rwo[DM * DM];
__device__ __align__(256) float g_q_lin[S_LEN * DM];
__device__ __align__(256) float g_k_lin[S_LEN * HKV_N * HD];
__device__ __align__(256) float g_v_lin[S_LEN * HKV_N * HD];
__device__ __align__(256) float g_qt[HQ * S_LEN * HD];
__device__ __align__(256) float g_kt[HKV_N * S_LEN * HD];
__device__ __align__(256) float g_ao[S_LEN * HQ * HD];

// ------------------------------ helpers -------------------------------------
__device__ __forceinline__ uint32_t smem_u32(const void* p) {
    uint32_t a;
    asm("{ .reg .u64 t; cvta.to.shared.u64 t, %1; cvt.u32.u64 %0, t; }"
        : "=r"(a) : "l"(p));
    return a;
}

__device__ __forceinline__ float round_tf32(float x) {
    uint32_t u;
    asm("cvt.rna.tf32.f32 %0, %1;" : "=r"(u) : "f"(x));
    return __uint_as_float(u);
}

__device__ __forceinline__ void mma_tf32(float* d, const uint32_t* a, const uint32_t* b) {
    asm volatile(
        "mma.sync.aligned.m16n8k8.row.col.f32.tf32.tf32.f32 "
        "{%0,%1,%2,%3}, {%4,%5,%6,%7}, {%8,%9}, {%0,%1,%2,%3};"
        : "+f"(d[0]), "+f"(d[1]), "+f"(d[2]), "+f"(d[3])
        : "r"(a[0]), "r"(a[1]), "r"(a[2]), "r"(a[3]), "r"(b[0]), "r"(b[1]));
}

#define CP_ASYNC16(dst, src) \
    asm volatile("cp.async.cg.shared.global [%0], [%1], 16;" :: "r"(dst), "l"(src) : "memory")
#define CP_COMMIT() asm volatile("cp.async.commit_group;" ::: "memory")
#define CP_WAIT(n)  asm volatile("cp.async.wait_group %0;" :: "n"(n) : "memory")

// -------- tf32 tensor-core GEMM: C[M,N] = A[M,K] * B[N,K]^T (mma.sync) -------
// A, B pre-rounded to tf32 values. 128x128 tile, KC=32, 2-stage cp.async.
__global__ __launch_bounds__(256, 1) void tc_gemm(
    const float* __restrict__ A, const float* __restrict__ B,
    float* __restrict__ C, int M, int N, int K)
{
    extern __shared__ float sm[];

    const int tid = threadIdx.x;
    const int wid = tid >> 5;
    const int lane = tid & 31;
    const int wm = wid & 1;          // 2 warps along M (64 each)
    const int wn = wid >> 1;         // 4 warps along N (32 each)
    const int g = lane >> 2;         // 0..7
    const int c = lane & 3;          // 0..3
    const int bm = blockIdx.y * TM;
    const int bn = blockIdx.x * TN;
    const int NCH = K >> 5;

    const uint32_t smA0 = smem_u32(sm);

    auto load_stage = [&](int kc, int s) {
        const uint32_t aAddr = smA0 + s * (STAGE_F * 4);
        const uint32_t bAddr = aAddr + A_STAGE * 4;
        #pragma unroll
        for (int t = 0; t < 8; t++) {
            const int idx = tid + 256 * t;          // 0..2047
            const bool isB = idx >= 1024;
            const int l = isB ? idx - 1024 : idx;
            const int row = l >> 3;
            const int seg = l & 7;
            const float* gp = (isB ? B + (size_t)(bn + row) * K
                                   : A + (size_t)(bm + row) * K) + kc * KC + seg * 4;
            const uint32_t dst = (isB ? bAddr : aAddr) + (row * LDP + seg * 4) * 4;
            CP_ASYNC16(dst, gp);
        }
    };

    float acc[4][4][4];
    #pragma unroll
    for (int i = 0; i < 4; i++)
        #pragma unroll
        for (int j = 0; j < 4; j++)
            #pragma unroll
            for (int r = 0; r < 4; r++) acc[i][j][r] = 0.f;

    load_stage(0, 0);
    CP_COMMIT();

    for (int ch = 0; ch < NCH; ch++) {
        const int s = ch & 1;
        if (ch + 1 < NCH) {
            load_stage(ch + 1, s ^ 1);
            CP_COMMIT();
            CP_WAIT(1);
        } else {
            CP_WAIT(0);
        }
        __syncthreads();

        const float* As = sm + s * STAGE_F;
        const float* Bs = As + A_STAGE;

        #pragma unroll
        for (int ks = 0; ks < 4; ks++) {
            uint32_t af[4][4], bf[4][2];
            #pragma unroll
            for (int i = 0; i < 4; i++) {
                const float* p = As + (wm * 64 + i * 16 + g) * LDP + ks * 8 + c;
                af[i][0] = __float_as_uint(p[0]);
                af[i][1] = __float_as_uint(p[8 * LDP]);
                af[i][2] = __float_as_uint(p[4]);
                af[i][3] = __float_as_uint(p[8 * LDP + 4]);
            }
            #pragma unroll
            for (int j = 0; j < 4; j++) {
                const float* p = Bs + (wn * 32 + j * 8 + g) * LDP + ks * 8 + c;
                bf[j][0] = __float_as_uint(p[0]);
                bf[j][1] = __float_as_uint(p[4]);
            }
            #pragma unroll
            for (int i = 0; i < 4; i++)
                #pragma unroll
                for (int j = 0; j < 4; j++)
                    mma_tf32(acc[i][j], af[i], bf[j]);
        }
        __syncthreads();
    }

    // epilogue: c0,c1 -> (row, 2c),(row,2c+1); c2,c3 -> row+8
    #pragma unroll
    for (int i = 0; i < 4; i++) {
        const int row0 = bm + wm * 64 + i * 16 + g;
        #pragma unroll
        for (int j = 0; j < 4; j++) {
            const int col = bn + wn * 32 + j * 8 + 2 * c;
            float2 v0 = make_float2(acc[i][j][0], acc[i][j][1]);
            float2 v1 = make_float2(acc[i][j][2], acc[i][j][3]);
            *reinterpret_cast<float2*>(C + (size_t)row0 * N + col) = v0;
            *reinterpret_cast<float2*>(C + (size_t)(row0 + 8) * N + col) = v1;
        }
    }
}

static const size_t GEMM_SMEM = (size_t)2 * STAGE_F * sizeof(float); // 73728

// ---------------- elementwise round-to-nearest tf32 --------------------------
__global__ __launch_bounds__(256) void round_tf32_kernel(
    const float* __restrict__ in, float* __restrict__ out, int n4)
{
    int i = blockIdx.x * blockDim.x + threadIdx.x;
    if (i < n4) {
        float4 v = reinterpret_cast<const float4*>(in)[i];
        float4 o;
        o.x = round_tf32(v.x); o.y = round_tf32(v.y);
        o.z = round_tf32(v.z); o.w = round_tf32(v.w);
        reinterpret_cast<float4*>(out)[i] = o;
    }
}

// --------------- RMSNorm over last dim (128) + transpose to [H][S][D] --------
__global__ __launch_bounds__(128) void rmsnorm_transpose(
    const float* __restrict__ in, const float* __restrict__ w,
    float* __restrict__ out, int rowStride)
{
    const int s = blockIdx.x;
    const int h = blockIdx.y;
    const int d = threadIdx.x;

    const float v = in[(size_t)s * rowStride + h * HD + d];
    float ss = v * v;
    #pragma unroll
    for (int off = 16; off; off >>= 1)
        ss += __shfl_xor_sync(0xffffffffu, ss, off);
    __shared__ float ws[4];
    if ((d & 31) == 0) ws[d >> 5] = ss;
    __syncthreads();
    const float tot = ws[0] + ws[1] + ws[2] + ws[3];
    const float inv = rsqrtf(tot * (1.0f / 128.0f) + 1e-6f);
    out[((size_t)h * S_LEN + s) * HD + d] = v * inv * w[d];
}

// --------------- flash attention with ALiBi + causal mask (GQA) --------------
__global__ __launch_bounds__(256) void attn_kernel(
    const float* __restrict__ Q, const float* __restrict__ Kt,
    const float* __restrict__ Vlin, float* __restrict__ O)
{
    extern __shared__ float smattn[];
    float* Qs = smattn;                  // [BM][129]
    float* Ks = Qs + BM * 129;           // [BN][129]
    float* Vs = Ks + BN * 129;           // [BN][HD]
    float* Ps = Vs + BN * HD;            // [BM][65]

    const int qt = blockIdx.x;
    const int h  = blockIdx.y;
    const int hk = h >> 2;
    const float slope = exp2f(-0.25f * (float)(h + 1));
    const float scale = 0.08838834764831845f;

    const int tid = threadIdx.x;
    const int tx = tid & 15;
    const int ty = tid >> 4;

    for (int idx = tid; idx < BM * HD / 4; idx += 256) {
        const int r = idx >> 5;
        const int c = (idx & 31) << 2;
        const float4 q4 = *reinterpret_cast<const float4*>(
            Q + ((size_t)h * S_LEN + (size_t)qt * BM + r) * HD + c);
        Qs[r * 129 + c + 0] = q4.x; Qs[r * 129 + c + 1] = q4.y;
        Qs[r * 129 + c + 2] = q4.z; Qs[r * 129 + c + 3] = q4.w;
    }

    float o_acc[4][8];
    float m_i[4], l_i[4];
    #pragma unroll
    for (int i = 0; i < 4; i++) {
        m_i[i] = -1e30f; l_i[i] = 0.f;
        #pragma unroll
        for (int m = 0; m < 8; m++) o_acc[i][m] = 0.f;
    }

    const int nkt = qt + 1;
    for (int kt = 0; kt < nkt; kt++) {
        __syncthreads();
        for (int idx = tid; idx < BN * HD / 4; idx += 256) {
            const int r = idx >> 5;
            const int c = (idx & 31) << 2;
            const float4 k4 = *reinterpret_cast<const float4*>(
                Kt + ((size_t)hk * S_LEN + (size_t)kt * BN + r) * HD + c);
            Ks[r * 129 + c + 0] = k4.x; Ks[r * 129 + c + 1] = k4.y;
            Ks[r * 129 + c + 2] = k4.z; Ks[r * 129 + c + 3] = k4.w;
            const float4 v4 = *reinterpret_cast<const float4*>(
                Vlin + ((size_t)(kt * BN + r)) * (HKV_N * HD) + hk * HD + c);
            Vs[r * HD + c + 0] = v4.x; Vs[r * HD + c + 1] = v4.y;
            Vs[r * HD + c + 2] = v4.z; Vs[r * HD + c + 3] = v4.w;
        }
        __syncthreads();

        float s_acc[4][4];
        #pragma unroll
        for (int i = 0; i < 4; i++)
            #pragma unroll
            for (int j = 0; j < 4; j++) s_acc[i][j] = 0.f;

        #pragma unroll 4
        for (int d = 0; d < HD; d++) {
            float qf[4], kf[4];
            #pragma unroll
            for (int i = 0; i < 4; i++) qf[i] = Qs[(ty + 16 * i) * 129 + d];
            #pragma unroll
            for (int j = 0; j < 4; j++) kf[j] = Ks[(tx + 16 * j) * 129 + d];
            #pragma unroll
            for (int i = 0; i < 4; i++)
                #pragma unroll
                for (int j = 0; j < 4; j++) s_acc[i][j] += qf[i] * kf[j];
        }

        const int q0 = qt * BM, k0 = kt * BN;
        #pragma unroll
        for (int i = 0; i < 4; i++) {
            const int qpos = q0 + ty + 16 * i;
            float rmax = -1e30f;
            #pragma unroll
            for (int j = 0; j < 4; j++) {
                const int kpos = k0 + tx + 16 * j;
                const float bias = (kpos > qpos) ? -1e30f
                                                 : slope * (float)(kpos - qpos);
                s_acc[i][j] = s_acc[i][j] * scale + bias;
                rmax = fmaxf(rmax, s_acc[i][j]);
            }
            #pragma unroll
            for (int off = 8; off; off >>= 1)
                rmax = fmaxf(rmax, __shfl_xor_sync(0xffffffffu, rmax, off));

            const float mnew = fmaxf(m_i[i], rmax);
            const float corr = __expf(m_i[i] - mnew);
            m_i[i] = mnew;

            float rsum = 0.f;
            #pragma unroll
            for (int j = 0; j < 4; j++) {
                const float p = __expf(s_acc[i][j] - mnew);
                Ps[(ty + 16 * i) * 65 + tx + 16 * j] = p;
                rsum += p;
            }
            #pragma unroll
            for (int off = 8; off; off >>= 1)
                rsum += __shfl_xor_sync(0xffffffffu, rsum, off);

            l_i[i] = l_i[i] * corr + rsum;
            #pragma unroll
            for (int m = 0; m < 8; m++) o_acc[i][m] *= corr;
        }
        __syncthreads();

        #pragma unroll 4
        for (int jj = 0; jj < BN; jj++) {
            float pf[4], vf[8];
            #pragma unroll
            for (int i = 0; i < 4; i++) pf[i] = Ps[(ty + 16 * i) * 65 + jj];
            #pragma unroll
            for (int m = 0; m < 8; m++) vf[m] = Vs[jj * HD + tx + 16 * m];
            #pragma unroll
            for (int i = 0; i < 4; i++)
                #pragma unroll
                for (int m = 0; m < 8; m++) o_acc[i][m] += pf[i] * vf[m];
        }
    }

    #pragma unroll
    for (int i = 0; i < 4; i++) {
        const float inv = 1.0f / l_i[i];
        const size_t r = (size_t)(qt * BM + ty + 16 * i);
        #pragma unroll
        for (int m = 0; m < 8; m++)
            O[r * (HQ * HD) + h * HD + tx + 16 * m] = round_tf32(o_acc[i][m] * inv);
    }
}

static const size_t ATTN_SMEM =
    (size_t)(BM * 129 + BN * 129 + BN * HD + BM * 65) * sizeof(float);

extern "C" void kernel_launch(void* const* d_in, const int* in_sizes, int n_in,
                              void* d_out, int out_size)
{
    (void)in_sizes; (void)n_in; (void)out_size;
    const float* x  = (const float*)d_in[0];
    const float* Wq = (const float*)d_in[1];
    const float* Wk = (const float*)d_in[2];
    const float* Wv = (const float*)d_in[3];
    const float* Wo = (const float*)d_in[4];
    const float* qw = (const float*)d_in[5];
    const float* kw = (const float*)d_in[6];
    float* out = (float*)d_out;

    float *rx, *rwq, *rwk, *rwv, *rwo, *q_lin, *k_lin, *v_lin, *qt_, *kt_, *ao;
    cudaGetSymbolAddress((void**)&rx,  g_rx);
    cudaGetSymbolAddress((void**)&rwq, g_rwq);
    cudaGetSymbolAddress((void**)&rwk, g_rwk);
    cudaGetSymbolAddress((void**)&rwv, g_rwv);
    cudaGetSymbolAddress((void**)&rwo, g_rwo);
    cudaGetSymbolAddress((void**)&q_lin, g_q_lin);
    cudaGetSymbolAddress((void**)&k_lin, g_k_lin);
    cudaGetSymbolAddress((void**)&v_lin, g_v_lin);
    cudaGetSymbolAddress((void**)&qt_,   g_qt);
    cudaGetSymbolAddress((void**)&kt_,   g_kt);
    cudaGetSymbolAddress((void**)&ao,    g_ao);

    cudaFuncSetAttribute(tc_gemm,
        cudaFuncAttributeMaxDynamicSharedMemorySize, (int)GEMM_SMEM);
    cudaFuncSetAttribute(attn_kernel,
        cudaFuncAttributeMaxDynamicSharedMemorySize, (int)ATTN_SMEM);

    // tf32 round-to-nearest prepass (kills truncation bias)
    {
        const int nx  = S_LEN * DM / 4;
        const int nwq = DM * DM / 4;
        const int nwk = HKV_N * HD * DM / 4;
        round_tf32_kernel<<<(nx  + 255) / 256, 256>>>(x,  rx,  nx);
        round_tf32_kernel<<<(nwq + 255) / 256, 256>>>(Wq, rwq, nwq);
        round_tf32_kernel<<<(nwk + 255) / 256, 256>>>(Wk, rwk, nwk);
        round_tf32_kernel<<<(nwk + 255) / 256, 256>>>(Wv, rwv, nwk);
        round_tf32_kernel<<<(nwq + 255) / 256, 256>>>(Wo, rwo, nwq);
    }

    // QKV projections on tf32 mma.sync
    tc_gemm<<<dim3(DM / TN, S_LEN / TM), 256, GEMM_SMEM>>>(
        rx, rwq, q_lin, S_LEN, DM, DM);
    tc_gemm<<<dim3((HKV_N * HD) / TN, S_LEN / TM), 256, GEMM_SMEM>>>(
        rx, rwk, k_lin, S_LEN, HKV_N * HD, DM);
    tc_gemm<<<dim3((HKV_N * HD) / TN, S_LEN / TM), 256, GEMM_SMEM>>>(
        rx, rwv, v_lin, S_LEN, HKV_N * HD, DM);

    rmsnorm_transpose<<<dim3(S_LEN, HQ), 128>>>(q_lin, qw, qt_, DM);
    rmsnorm_transpose<<<dim3(S_LEN, HKV_N), 128>>>(k_lin, kw, kt_, HKV_N * HD);

    attn_kernel<<<dim3(S_LEN / BM, HQ), 256, ATTN_SMEM>>>(qt_, kt_, v_lin, ao);

    // output projection (ao already tf32-rounded in attn epilogue)
    tc_gemm<<<dim3(DM / TN, S_LEN / TM), 256, GEMM_SMEM>>>(
        ao, rwo, out, S_LEN, DM, DM);
}